// round 10
// baseline (speedup 1.0000x reference)
#include <cuda_runtime.h>
#include <math_constants.h>

#define HH 1024
#define WW 1024
#define CC 128
#define NITER 8
#define TS 32                 // tile side; grid = 1024 tiles, 1 per CTA
#define TWO_RHO 43.85f        // 2*sqrt(2)*15.5 (tile half-diagonal), rounded up
#define FULLM 0xFFFFFFFFu
#define NBLK 1024

// 4 rotating cluster position buffers (row,col interleaved).
// Invariant: g_pos[1] is all-zero at kernel_launch entry (static zero-init
// covers the first run; launch k=7 re-zeroes it for the next graph replay).
__device__ float g_pos[4][2 * CC];

// warp-wide min of a uint (nonneg float bits are order-isomorphic)
__device__ __forceinline__ unsigned warp_min_u32(unsigned v) {
    unsigned r;
    asm volatile("redux.sync.min.u32 %0, %1, 0xffffffff;" : "=r"(r) : "r"(v));
    return r;
}

// One iteration per launch; the kernel boundary is the grid barrier.
// zbuf (may be null): buffer used as OUTPUT by the NEXT launch — idle in this
// one, so block 0 zeroing it is race-free and is published by kernel teardown.
__global__ __launch_bounds__(256) void km_iter_kernel(
    const float* __restrict__ heatmap,
    const float* __restrict__ cin,
    float* __restrict__ cout,
    float* __restrict__ zbuf)
{
    __shared__ float2 s_cand[CC];
    __shared__ int    s_cidx[CC];
    __shared__ float  s_acc[2 * CC];
    __shared__ int    s_n;

    const int t = threadIdx.x;
    const int wid = t >> 5;
    const int lane = t & 31;
    const int tile_c = (blockIdx.x & 31) * TS;
    const int tile_r = (blockIdx.x >> 5) * TS;
    const int row  = tile_r + (t >> 3);
    const int col0 = tile_c + (t & 7) * 4;
    const float frow = (float)row;
    const float fc0 = (float)col0;
    const float fc1 = fc0 + 1.0f;
    const float fc2 = fc0 + 2.0f;
    const float fc3 = fc0 + 3.0f;

    if (zbuf != nullptr && blockIdx.x == 0) zbuf[t] = 0.0f;
    s_acc[t] = 0.0f;

    // issue the heatmap load early (L2-resident; L1 is flushed per launch)
    const float4 h4 = *reinterpret_cast<const float4*>(heatmap + row * WW + col0);

    // ---- Phase A (warp 0 only): cull + O(1) zero-dup + compaction ----
    if (wid == 0) {
        const float cy = (float)tile_r + 15.5f;
        const float cx = (float)tile_c + 15.5f;
        const float2* cin2 = reinterpret_cast<const float2*>(cin);
        float2 c4[4];
        float  d2[4];
        float m = CUDART_INF_F;
        #pragma unroll
        for (int q = 0; q < 4; ++q) {
            // L2 load: positions were produced by global atomics (prev launch)
            c4[q] = __ldcg(cin2 + q * 32 + lane);
            const float dr = cy - c4[q].x, dc = cx - c4[q].y;
            d2[q] = fmaf(dr, dr, dc * dc);
            m = fminf(m, d2[q]);
        }
        const float md2 = __uint_as_float(warp_min_u32(__float_as_uint(m)));

        // first exactly-(0,0) cluster (empty clusters collapse there);
        // later (0,0) dups can never win strict-< argmin -> drop them.
        // Other bitwise dups are rare and harmless (strict < keeps first).
        unsigned zb[4];
        #pragma unroll
        for (int q = 0; q < 4; ++q)
            zb[q] = __ballot_sync(FULLM, (c4[q].x == 0.0f) && (c4[q].y == 0.0f));
        int firstZero = 1 << 30;
        #pragma unroll
        for (int q = 3; q >= 0; --q)
            if (zb[q]) firstZero = q * 32 + (__ffs(zb[q]) - 1);

        // cluster can win argmin for some pixel in tile only if
        // d(center,c) <= minD + 2*rho; margin keeps fp error conservative
        const float minD = sqrtf(md2);
        const float thr  = minD + TWO_RHO + 4.0f + 1e-5f * minD;
        const float thr2 = thr * thr;

        int base = 0;
        #pragma unroll
        for (int q = 0; q < 4; ++q) {             // ascending q keeps index order
            const int ci = q * 32 + lane;
            const bool zz = (zb[q] >> lane) & 1u;
            const bool keep = (d2[q] <= thr2) && !(zz && ci != firstZero);
            const unsigned bq = __ballot_sync(FULLM, keep);
            if (keep) {
                const int rank = base + __popc(bq & ((1u << lane) - 1u));
                s_cand[rank] = c4[q];
                s_cidx[rank] = ci;
            }
            base += __popc(bq);
        }
        if (lane == 0) s_n = base;
    }
    __syncthreads();
    const int ncand = s_n;

    // ---- Phase B: per-pixel argmin (candidates in index order) ----
    float b0 = CUDART_INF_F, b1 = CUDART_INF_F, b2 = CUDART_INF_F, b3 = CUDART_INF_F;
    int k0 = 0, k1 = 0, k2 = 0, k3 = 0;

    #pragma unroll 2
    for (int j = 0; j < ncand; ++j) {
        const float2 cl = s_cand[j];
        const float dr = frow - cl.x;
        const float dr2 = dr * dr;
        float dc, d;
        // ordering of max(1,sqrt(d2)) == ordering of max(1,d2); strict <
        dc = fc0 - cl.y; d = fmaxf(fmaf(dc, dc, dr2), 1.0f);
        if (d < b0) { b0 = d; k0 = j; }
        dc = fc1 - cl.y; d = fmaxf(fmaf(dc, dc, dr2), 1.0f);
        if (d < b1) { b1 = d; k1 = j; }
        dc = fc2 - cl.y; d = fmaxf(fmaf(dc, dc, dr2), 1.0f);
        if (d < b2) { b2 = d; k2 = j; }
        dc = fc3 - cl.y; d = fmaxf(fmaf(dc, dc, dr2), 1.0f);
        if (d < b3) { b3 = d; k3 = j; }
    }

    const int i0 = s_cidx[k0];
    const int i1 = s_cidx[k1];
    const int i2 = s_cidx[k2];
    const int i3 = s_cidx[k3];

    // weight = heatmap / max(1, sqrt(d2)) = h * rsqrt(clamped d2)
    const float w0 = h4.x * rsqrtf(b0);
    const float w1 = h4.y * rsqrtf(b1);
    const float w2 = h4.z * rsqrtf(b2);
    const float w3 = h4.w * rsqrtf(b3);

    // ---- scatter: uniform-warp fast path, run-length fallback ----
    const bool uni4 = (i0 == i1) & (i1 == i2) & (i2 == i3);
    const int  u    = __shfl_sync(FULLM, i0, 0);
    const bool alluni = __all_sync(FULLM, uni4 && (i0 == u));

    if (alluni) {
        float rsum = frow * ((w0 + w1) + (w2 + w3));
        float csum = (fc0 * w0 + fc1 * w1) + (fc2 * w2 + fc3 * w3);
        #pragma unroll
        for (int o = 16; o; o >>= 1) {
            rsum += __shfl_xor_sync(FULLM, rsum, o);
            csum += __shfl_xor_sync(FULLM, csum, o);
        }
        if (lane == 0) {
            atomicAdd(&s_acc[2 * u],     rsum);
            atomicAdd(&s_acc[2 * u + 1], csum);
        }
    } else {
        int cur = i0;
        float wsum = w0, cwsum = fc0 * w0;
        #define KM_STEP(ii, ww, fcx)                                    \
            if ((ii) == cur) { wsum += (ww); cwsum += (fcx) * (ww); }   \
            else {                                                      \
                atomicAdd(&s_acc[2 * cur],     frow * wsum);            \
                atomicAdd(&s_acc[2 * cur + 1], cwsum);                  \
                cur = (ii); wsum = (ww); cwsum = (fcx) * (ww);          \
            }
        KM_STEP(i1, w1, fc1)
        KM_STEP(i2, w2, fc2)
        KM_STEP(i3, w3, fc3)
        #undef KM_STEP
        atomicAdd(&s_acc[2 * cur],     frow * wsum);
        atomicAdd(&s_acc[2 * cur + 1], cwsum);
    }

    __syncthreads();
    // global accumulate; skip zeros (all contributions are >= +0)
    const float v = s_acc[t];
    if (v != 0.0f) atomicAdd(&cout[t], v);
}

extern "C" void kernel_launch(void* const* d_in, const int* in_sizes, int n_in,
                              void* d_out, int out_size) {
    const float* clusters = (const float*)d_in[0];
    const float* heatmap  = (const float*)d_in[1];
    if (n_in >= 2 && in_sizes[0] != 2 * CC) {
        const float* tmp = clusters; clusters = heatmap; heatmap = tmp;
    }
    float* out = (float*)d_out;

    float* base = nullptr;
    cudaGetSymbolAddress((void**)&base, g_pos);
    float* B[4] = { base, base + 2 * CC, base + 4 * CC, base + 6 * CC };

    // launch k: reads (k==0 ? clusters : B[k&3]), writes B[(k+1)&3] (k=7: out).
    // zbuf[k] = output buffer of launch k+1 (idle during launch k):
    //   k<=5 : B[(k+2)&3]
    //   k==6 : d_out (written by k=7)
    //   k==7 : B[1]  (restores entry invariant for the next graph replay)
    for (int k = 0; k < NITER; ++k) {
        const float* cin = (k == 0) ? clusters : B[k & 3];
        float* cout = (k == NITER - 1) ? out : B[(k + 1) & 3];
        float* zbuf;
        if (k <= 5)      zbuf = B[(k + 2) & 3];
        else if (k == 6) zbuf = out;
        else             zbuf = B[1];
        km_iter_kernel<<<NBLK, 256>>>(heatmap, cin, cout, zbuf);
    }
}